// round 7
// baseline (speedup 1.0000x reference)
#include <cuda_runtime.h>
#include <cstdint>
#include <cstring>

// Problem constants
#define BATCH 65536
#define KD    784
#define F1    48
#define F2    24
#define F3    10
#define NBLK  512           // BATCH / 128

// ---------------- scratch (device globals; no allocations allowed) ----------
__device__ __align__(16) float g_y1[BATCH * F1];
__device__ __align__(16) float g_y2[BATCH * F2];
__device__ float g_part1[NBLK][F1][2];
__device__ float g_part2[NBLK][F2][2];
__device__ float g_sc1[F1], g_sh1[F1], g_msu1[2];
__device__ float g_sc2[F2], g_sh2[F2], g_msu2[2];

// ---------------- Threefry2x32 (bit-exact JAX) ------------------------------
__host__ __device__ __forceinline__ void tf2x32(uint32_t k0, uint32_t k1,
                                                uint32_t x0, uint32_t x1,
                                                uint32_t& o0, uint32_t& o1) {
  uint32_t ks2 = k0 ^ k1 ^ 0x1BD11BDAu;
  x0 += k0; x1 += k1;
#define TFR(r) { x0 += x1; x1 = (x1 << (r)) | (x1 >> (32 - (r))); x1 ^= x0; }
  TFR(13) TFR(15) TFR(26) TFR(6)
  x0 += k1;  x1 += ks2 + 1u;
  TFR(17) TFR(29) TFR(16) TFR(24)
  x0 += ks2; x1 += k0 + 2u;
  TFR(13) TFR(15) TFR(26) TFR(6)
  x0 += k0;  x1 += k1 + 3u;
  TFR(17) TFR(29) TFR(16) TFR(24)
  x0 += k1;  x1 += ks2 + 4u;
  TFR(13) TFR(15) TFR(26) TFR(6)
  x0 += ks2; x1 += k0 + 5u;
#undef TFR
  o0 = x0; o1 = x1;
}

// JAX partitionable random_bits for 32-bit, element index e (< 2^32):
// counts = (hi64(e)=0, lo64(e)=e); bits = out0 ^ out1.
__device__ __forceinline__ uint32_t jax_bits32(uint32_t k0, uint32_t k1,
                                               uint32_t e) {
  uint32_t o0, o1;
  tf2x32(k0, k1, 0u, e, o0, o1);
  return o0 ^ o1;
}

// XLA/Giles single-precision erfinv (matches jax.lax.erf_inv f32 path)
__device__ __forceinline__ float jax_erfinv(float x) {
  float w = -log1pf(-x * x);
  float p;
  if (w < 5.0f) {
    w -= 2.5f;
    p = 2.81022636e-08f;
    p = fmaf(p, w, 3.43273939e-07f);
    p = fmaf(p, w, -3.5233877e-06f);
    p = fmaf(p, w, -4.39150654e-06f);
    p = fmaf(p, w, 0.00021858087f);
    p = fmaf(p, w, -0.00125372503f);
    p = fmaf(p, w, -0.00417768164f);
    p = fmaf(p, w, 0.246640727f);
    p = fmaf(p, w, 1.50140941f);
  } else {
    w = sqrtf(w) - 3.0f;
    p = -0.000200214257f;
    p = fmaf(p, w, 0.000100950558f);
    p = fmaf(p, w, 0.00134934322f);
    p = fmaf(p, w, -0.00367342844f);
    p = fmaf(p, w, 0.00573950773f);
    p = fmaf(p, w, -0.0076224613f);
    p = fmaf(p, w, 0.00943887047f);
    p = fmaf(p, w, 1.00167406f);
    p = fmaf(p, w, 2.83297682f);
  }
  return p * x;
}

// jax.random.normal from one 32-bit draw: sqrt(2)*erfinv(uniform(lo=-1+ulp, 1))
__device__ __forceinline__ float jax_normal(uint32_t bits) {
  float u = __uint_as_float((bits >> 9) | 0x3f800000u) - 1.0f;  // [0,1)
  float r = fmaf(u, 2.0f, -0.99999994f);   // (hi-lo) rounds to 2.0f in f32
  r = fmaxf(-0.99999994f, r);
  return 1.41421356f * jax_erfinv(r);
}

// ---------------- K1: GEMM1 (x @ w1^T + b1) + per-feature partial stats -----
// BM=128 rows/block, BN=48 (full), BK=16. 256 threads: 16x16, each 8 rows x 3 cols.
__global__ __launch_bounds__(256) void gemm1_kernel(const float* __restrict__ x,
                                                    const float* __restrict__ w1,
                                                    const float* __restrict__ b1) {
  __shared__ __align__(16) float As[16][128];
  __shared__ __align__(16) float Ws[16][F1];
  __shared__ float2 red[F1][16];

  const int tid = threadIdx.x;
  const int ty = tid >> 4, tx = tid & 15;
  const int row0 = blockIdx.x * 128;

  float acc[8][3];
#pragma unroll
  for (int i = 0; i < 8; i++)
#pragma unroll
    for (int j = 0; j < 3; j++) acc[i][j] = 0.0f;

  for (int kt = 0; kt < KD; kt += 16) {
    // x tile: 128 rows x 16 k (512 float4), transposed into As[k][row]
#pragma unroll
    for (int l = 0; l < 2; l++) {
      int idx = tid + l * 256;
      int r = idx >> 2, kq = (idx & 3) * 4;
      float4 v = *reinterpret_cast<const float4*>(
          x + (size_t)(row0 + r) * KD + kt + kq);
      As[kq + 0][r] = v.x; As[kq + 1][r] = v.y;
      As[kq + 2][r] = v.z; As[kq + 3][r] = v.w;
    }
    // w tile: 48 x 16 (192 float4) into Ws[k][nf]
    if (tid < 192) {
      int nf = tid >> 2, kq = (tid & 3) * 4;
      float4 v = *reinterpret_cast<const float4*>(
          w1 + (size_t)nf * KD + kt + kq);
      Ws[kq + 0][nf] = v.x; Ws[kq + 1][nf] = v.y;
      Ws[kq + 2][nf] = v.z; Ws[kq + 3][nf] = v.w;
    }
    __syncthreads();
#pragma unroll
    for (int k = 0; k < 16; k++) {
      float4 a03 = *reinterpret_cast<const float4*>(&As[k][ty * 8 + 0]);
      float4 a47 = *reinterpret_cast<const float4*>(&As[k][ty * 8 + 4]);
      float wv0 = Ws[k][tx * 3 + 0];
      float wv1 = Ws[k][tx * 3 + 1];
      float wv2 = Ws[k][tx * 3 + 2];
      acc[0][0] = fmaf(a03.x, wv0, acc[0][0]);
      acc[0][1] = fmaf(a03.x, wv1, acc[0][1]);
      acc[0][2] = fmaf(a03.x, wv2, acc[0][2]);
      acc[1][0] = fmaf(a03.y, wv0, acc[1][0]);
      acc[1][1] = fmaf(a03.y, wv1, acc[1][1]);
      acc[1][2] = fmaf(a03.y, wv2, acc[1][2]);
      acc[2][0] = fmaf(a03.z, wv0, acc[2][0]);
      acc[2][1] = fmaf(a03.z, wv1, acc[2][1]);
      acc[2][2] = fmaf(a03.z, wv2, acc[2][2]);
      acc[3][0] = fmaf(a03.w, wv0, acc[3][0]);
      acc[3][1] = fmaf(a03.w, wv1, acc[3][1]);
      acc[3][2] = fmaf(a03.w, wv2, acc[3][2]);
      acc[4][0] = fmaf(a47.x, wv0, acc[4][0]);
      acc[4][1] = fmaf(a47.x, wv1, acc[4][1]);
      acc[4][2] = fmaf(a47.x, wv2, acc[4][2]);
      acc[5][0] = fmaf(a47.y, wv0, acc[5][0]);
      acc[5][1] = fmaf(a47.y, wv1, acc[5][1]);
      acc[5][2] = fmaf(a47.y, wv2, acc[5][2]);
      acc[6][0] = fmaf(a47.z, wv0, acc[6][0]);
      acc[6][1] = fmaf(a47.z, wv1, acc[6][1]);
      acc[6][2] = fmaf(a47.z, wv2, acc[6][2]);
      acc[7][0] = fmaf(a47.w, wv0, acc[7][0]);
      acc[7][1] = fmaf(a47.w, wv1, acc[7][1]);
      acc[7][2] = fmaf(a47.w, wv2, acc[7][2]);
    }
    __syncthreads();
  }

  // epilogue: add bias, store y1, reduce per-column sum/sumsq
  float bias[3], cs[3] = {0.f, 0.f, 0.f}, css[3] = {0.f, 0.f, 0.f};
#pragma unroll
  for (int j = 0; j < 3; j++) bias[j] = b1[tx * 3 + j];
#pragma unroll
  for (int i = 0; i < 8; i++) {
#pragma unroll
    for (int j = 0; j < 3; j++) {
      float y = acc[i][j] + bias[j];
      int r = ty * 8 + i;
      g_y1[(size_t)(row0 + r) * F1 + tx * 3 + j] = y;
      cs[j] += y;
      css[j] += y * y;
    }
  }
#pragma unroll
  for (int j = 0; j < 3; j++) red[tx * 3 + j][ty] = make_float2(cs[j], css[j]);
  __syncthreads();
  if (tid < F1) {
    float s = 0.f, ss = 0.f;
#pragma unroll
    for (int t = 0; t < 16; t++) { s += red[tid][t].x; ss += red[tid][t].y; }
    g_part1[blockIdx.x][tid][0] = s;
    g_part1[blockIdx.x][tid][1] = ss;
  }
}

// ---------------- finalize: BN params + analytic global mean/std*u ----------
__global__ void finalize_kernel(int layer, const float* __restrict__ gamma,
                                const float* __restrict__ beta, float uval) {
  const int F = (layer == 1) ? F1 : F2;
  const float* base = (layer == 1) ? &g_part1[0][0][0] : &g_part2[0][0][0];
  __shared__ float contrib[F1], betas[F1];
  int f = threadIdx.x;
  if (f < F) {
    float s0 = 0, s1 = 0, s2 = 0, s3 = 0, q0 = 0, q1 = 0, q2 = 0, q3 = 0;
    for (int b = 0; b < NBLK; b += 4) {
      const float* p0 = base + ((size_t)(b + 0) * F + f) * 2;
      const float* p1 = base + ((size_t)(b + 1) * F + f) * 2;
      const float* p2 = base + ((size_t)(b + 2) * F + f) * 2;
      const float* p3 = base + ((size_t)(b + 3) * F + f) * 2;
      s0 += p0[0]; q0 += p0[1];
      s1 += p1[0]; q1 += p1[1];
      s2 += p2[0]; q2 += p2[1];
      s3 += p3[0]; q3 += p3[1];
    }
    double s = (double)s0 + s1 + s2 + s3;
    double ss = (double)q0 + q1 + q2 + q3;
    double mean = s / 65536.0;
    double var = ss / 65536.0 - mean * mean;
    double rr = 1.0 / sqrt(var + 1e-5);
    double g = (double)gamma[f];
    if (layer == 1) {
      g_sc1[f] = (float)(g * rr);
      g_sh1[f] = (float)((double)beta[f] - mean * g * rr);
    } else {
      g_sc2[f] = (float)(g * rr);
      g_sh2[f] = (float)((double)beta[f] - mean * g * rr);
    }
    contrib[f] = (float)(g * g * var / (var + 1e-5));
    betas[f] = beta[f];
  }
  __syncthreads();
  if (f == 0) {
    float bm = 0.f;
    for (int i = 0; i < F; i++) bm += betas[i];
    bm /= (float)F;
    double acc = 0.0;
    for (int i = 0; i < F; i++) {
      double d = (double)betas[i] - bm;
      acc += (double)contrib[i] + d * d;
    }
    double ntot = 65536.0 * (double)F;
    double s2 = 65536.0 * acc / (ntot - 1.0);
    float* msu = (layer == 1) ? g_msu1 : g_msu2;
    msu[0] = bm;                       // global mean of BN output (= mean(beta))
    msu[1] = (float)sqrt(s2) * uval;   // std(ddof=1) * U(1,2)
  }
}

// ---------------- K3: BN1 + noise + relu + GEMM2 + partial stats ------------
__global__ __launch_bounds__(128) void layer2_kernel(const float* __restrict__ w2,
                                                     const float* __restrict__ b2,
                                                     uint32_t kn0, uint32_t kn1) {
  __shared__ __align__(16) float ys[128][49];   // padded: conflict-free row reads
  __shared__ __align__(16) float w2s[F2][F1];
  __shared__ float b2s[F2];
  __shared__ float sc[F1], sh[F1];
  __shared__ __align__(16) float outs[128][F2];

  const int tid = threadIdx.x;
  const int row0 = blockIdx.x * 128;

  const float4* src = reinterpret_cast<const float4*>(g_y1 + (size_t)row0 * F1);
#pragma unroll
  for (int l = 0; l < 12; l++) {
    int idx = tid + l * 128;              // 1536 float4
    float4 v = src[idx];
    int fi = idx * 4, r = fi / F1, c = fi % F1;
    ys[r][c] = v.x; ys[r][c + 1] = v.y; ys[r][c + 2] = v.z; ys[r][c + 3] = v.w;
  }
#pragma unroll
  for (int l = 0; l < 3; l++) {
    int idx = tid + l * 128;
    if (idx < (F2 * F1) / 4) {
      float4 v = reinterpret_cast<const float4*>(w2)[idx];
      float* dst = &w2s[0][0] + idx * 4;
      dst[0] = v.x; dst[1] = v.y; dst[2] = v.z; dst[3] = v.w;
    }
  }
  if (tid < F2) b2s[tid] = b2[tid];
  if (tid < F1) { sc[tid] = g_sc1[tid]; sh[tid] = g_sh1[tid]; }
  const float m1 = g_msu1[0], su1 = g_msu1[1];
  __syncthreads();

  const int grow = row0 + tid;
  const uint32_t ebase = (uint32_t)grow * (uint32_t)F1;
  float acc[F2];
#pragma unroll
  for (int j = 0; j < F2; j++) acc[j] = b2s[j];

  for (int c = 0; c < F1; c++) {
    float z = fmaf(ys[tid][c], sc[c], sh[c]);
    uint32_t bits = jax_bits32(kn0, kn1, ebase + (uint32_t)c);
    float h = fmaxf(z + fmaf(su1, jax_normal(bits), m1), 0.0f);
#pragma unroll
    for (int j = 0; j < F2; j++) acc[j] = fmaf(h, w2s[j][c], acc[j]);
  }
#pragma unroll
  for (int j = 0; j < F2; j++) outs[tid][j] = acc[j];
  __syncthreads();

  if (tid < F2) {
    float s = 0.f, ss = 0.f;
    for (int r = 0; r < 128; r++) {
      float v = outs[r][tid];
      s += v; ss += v * v;
    }
    g_part2[blockIdx.x][tid][0] = s;
    g_part2[blockIdx.x][tid][1] = ss;
  }
  float4* dst = reinterpret_cast<float4*>(g_y2 + (size_t)row0 * F2);
  const float4* osrc = reinterpret_cast<const float4*>(&outs[0][0]);
#pragma unroll
  for (int l = 0; l < 6; l++) dst[tid + l * 128] = osrc[tid + l * 128];
}

// ---------------- K5: BN2 + noise + relu + GEMM3 -> out ---------------------
__global__ __launch_bounds__(128) void layer3_kernel(const float* __restrict__ w3,
                                                     const float* __restrict__ b3,
                                                     float* __restrict__ out,
                                                     uint32_t kn0, uint32_t kn1) {
  __shared__ __align__(16) float ys[128][25];
  __shared__ float w3s[F3][F2];
  __shared__ float b3s[F3];
  __shared__ float sc[F2], sh[F2];
  __shared__ __align__(16) float outs[128][F3];

  const int tid = threadIdx.x;
  const int row0 = blockIdx.x * 128;

  const float4* src = reinterpret_cast<const float4*>(g_y2 + (size_t)row0 * F2);
#pragma unroll
  for (int l = 0; l < 6; l++) {
    int idx = tid + l * 128;              // 768 float4
    float4 v = src[idx];
    int fi = idx * 4, r = fi / F2, c = fi % F2;
    ys[r][c] = v.x; ys[r][c + 1] = v.y; ys[r][c + 2] = v.z; ys[r][c + 3] = v.w;
  }
  // w3 has F3*F2 = 240 elements but only 128 threads: TWO iterations.
  // (Round<=3 bug: single `if (tid < 240)` left w3s[128..239] uninitialized.)
#pragma unroll
  for (int l = 0; l < 2; l++) {
    int idx = tid + l * 128;
    if (idx < F3 * F2) (&w3s[0][0])[idx] = w3[idx];
  }
  if (tid < F3) b3s[tid] = b3[tid];
  if (tid < F2) { sc[tid] = g_sc2[tid]; sh[tid] = g_sh2[tid]; }
  const float m2 = g_msu2[0], su2 = g_msu2[1];
  __syncthreads();

  const int grow = row0 + tid;
  const uint32_t ebase = (uint32_t)grow * (uint32_t)F2;
  float acc[F3];
#pragma unroll
  for (int j = 0; j < F3; j++) acc[j] = b3s[j];

  for (int c = 0; c < F2; c++) {
    float z = fmaf(ys[tid][c], sc[c], sh[c]);
    uint32_t bits = jax_bits32(kn0, kn1, ebase + (uint32_t)c);
    float h = fmaxf(z + fmaf(su2, jax_normal(bits), m2), 0.0f);
#pragma unroll
    for (int j = 0; j < F3; j++) acc[j] = fmaf(h, w3s[j][c], acc[j]);
  }
#pragma unroll
  for (int j = 0; j < F3; j++) outs[tid][j] = acc[j];
  __syncthreads();

  float* dst = out + (size_t)row0 * F3;
  const float* osrc = &outs[0][0];
#pragma unroll
  for (int l = 0; l < F3; l++) dst[tid + l * 128] = osrc[tid + l * 128];
}

// ---------------- host: derive JAX subkeys + uniform scalars ----------------
// JAX >= 0.4.36: jax_threefry_partitionable defaults to True.
//   split(key)[i]   = full output pair of threefry(key, (0, i))
//   bits32(key, e)  = out0 ^ out1 of threefry(key, (0, e))
static void derive_keys(uint32_t seed, uint32_t& kn0, uint32_t& kn1, float& uval) {
  uint32_t k0 = 0u, k1 = seed;
  uint32_t a0, a1, b0, b1;
  tf2x32(k0, k1, 0u, 0u, a0, a1);   // subkey 0 = ku
  tf2x32(k0, k1, 0u, 1u, b0, b1);   // subkey 1 = kn
  kn0 = b0; kn1 = b1;
  uint32_t u0, u1;
  tf2x32(a0, a1, 0u, 0u, u0, u1);   // random_bits(ku, shape=())
  uint32_t bits = u0 ^ u1;
  uint32_t fb = (bits >> 9) | 0x3f800000u;
  float f;
  memcpy(&f, &fb, sizeof(float));
  uval = f;   // uniform(ku, (), minval=1, maxval=2) = [1,2) mantissa draw
}

extern "C" void kernel_launch(void* const* d_in, const int* in_sizes, int n_in,
                              void* d_out, int out_size) {
  const float* x      = (const float*)d_in[0];
  const float* w1     = (const float*)d_in[1];
  const float* b1     = (const float*)d_in[2];
  const float* gamma1 = (const float*)d_in[3];
  const float* beta1  = (const float*)d_in[4];
  const float* w2     = (const float*)d_in[5];
  const float* b2     = (const float*)d_in[6];
  const float* gamma2 = (const float*)d_in[7];
  const float* beta2  = (const float*)d_in[8];
  const float* w3     = (const float*)d_in[9];
  const float* b3     = (const float*)d_in[10];
  float* out = (float*)d_out;

  uint32_t kn10, kn11, kn20, kn21;
  float u1, u2;
  derive_keys(1234u, kn10, kn11, u1);
  derive_keys(5678u, kn20, kn21, u2);

  gemm1_kernel<<<NBLK, 256>>>(x, w1, b1);
  finalize_kernel<<<1, 64>>>(1, gamma1, beta1, u1);
  layer2_kernel<<<NBLK, 128>>>(w2, b2, kn10, kn11);
  finalize_kernel<<<1, 64>>>(2, gamma2, beta2, u2);
  layer3_kernel<<<NBLK, 128>>>(w3, b3, out, kn20, kn21);
}

// round 8
// speedup vs baseline: 1.0027x; 1.0027x over previous
#include <cuda_runtime.h>
#include <cstdint>
#include <cstring>

// Problem constants
#define BATCH 65536
#define KD    784
#define F1    48
#define F2    24
#define F3    10
#define NBLK  512           // BATCH / 128

// ---------------- scratch (device globals; no allocations allowed) ----------
__device__ __align__(16) float g_y1[BATCH * F1];
__device__ __align__(16) float g_y2[BATCH * F2];
__device__ float g_part1[NBLK][F1][2];
__device__ float g_part2[NBLK][F2][2];
__device__ float g_sc1[F1], g_sh1[F1], g_msu1[2];
__device__ float g_sc2[F2], g_sh2[F2], g_msu2[2];

// ---------------- Threefry2x32 (bit-exact JAX) ------------------------------
__host__ __device__ __forceinline__ void tf2x32(uint32_t k0, uint32_t k1,
                                                uint32_t x0, uint32_t x1,
                                                uint32_t& o0, uint32_t& o1) {
  uint32_t ks2 = k0 ^ k1 ^ 0x1BD11BDAu;
  x0 += k0; x1 += k1;
#define TFR(r) { x0 += x1; x1 = (x1 << (r)) | (x1 >> (32 - (r))); x1 ^= x0; }
  TFR(13) TFR(15) TFR(26) TFR(6)
  x0 += k1;  x1 += ks2 + 1u;
  TFR(17) TFR(29) TFR(16) TFR(24)
  x0 += ks2; x1 += k0 + 2u;
  TFR(13) TFR(15) TFR(26) TFR(6)
  x0 += k0;  x1 += k1 + 3u;
  TFR(17) TFR(29) TFR(16) TFR(24)
  x0 += k1;  x1 += ks2 + 4u;
  TFR(13) TFR(15) TFR(26) TFR(6)
  x0 += ks2; x1 += k0 + 5u;
#undef TFR
  o0 = x0; o1 = x1;
}

// JAX partitionable random_bits for 32-bit, element index e (< 2^32):
// counts = (hi64(e)=0, lo64(e)=e); bits = out0 ^ out1.
__device__ __forceinline__ uint32_t jax_bits32(uint32_t k0, uint32_t k1,
                                               uint32_t e) {
  uint32_t o0, o1;
  tf2x32(k0, k1, 0u, e, o0, o1);
  return o0 ^ o1;
}

// XLA/Giles single-precision erfinv (matches jax.lax.erf_inv f32 path)
__device__ __forceinline__ float jax_erfinv(float x) {
  float w = -log1pf(-x * x);
  float p;
  if (w < 5.0f) {
    w -= 2.5f;
    p = 2.81022636e-08f;
    p = fmaf(p, w, 3.43273939e-07f);
    p = fmaf(p, w, -3.5233877e-06f);
    p = fmaf(p, w, -4.39150654e-06f);
    p = fmaf(p, w, 0.00021858087f);
    p = fmaf(p, w, -0.00125372503f);
    p = fmaf(p, w, -0.00417768164f);
    p = fmaf(p, w, 0.246640727f);
    p = fmaf(p, w, 1.50140941f);
  } else {
    w = sqrtf(w) - 3.0f;
    p = -0.000200214257f;
    p = fmaf(p, w, 0.000100950558f);
    p = fmaf(p, w, 0.00134934322f);
    p = fmaf(p, w, -0.00367342844f);
    p = fmaf(p, w, 0.00573950773f);
    p = fmaf(p, w, -0.0076224613f);
    p = fmaf(p, w, 0.00943887047f);
    p = fmaf(p, w, 1.00167406f);
    p = fmaf(p, w, 2.83297682f);
  }
  return p * x;
}

// jax.random.normal from one 32-bit draw: sqrt(2)*erfinv(uniform(lo=-1+ulp, 1))
__device__ __forceinline__ float jax_normal(uint32_t bits) {
  float u = __uint_as_float((bits >> 9) | 0x3f800000u) - 1.0f;  // [0,1)
  float r = fmaf(u, 2.0f, -0.99999994f);   // (hi-lo) rounds to 2.0f in f32
  r = fmaxf(-0.99999994f, r);
  return 1.41421356f * jax_erfinv(r);
}

// ---------------- K1: GEMM1 (x @ w1^T + b1) + per-feature partial stats -----
// BM=128 rows/block, BN=48 (full), BK=16. 256 threads: 16x16, each 8 rows x 3 cols.
__global__ __launch_bounds__(256) void gemm1_kernel(const float* __restrict__ x,
                                                    const float* __restrict__ w1,
                                                    const float* __restrict__ b1) {
  __shared__ __align__(16) float As[16][128];
  __shared__ __align__(16) float Ws[16][F1];
  __shared__ float2 red[F1][16];

  const int tid = threadIdx.x;
  const int ty = tid >> 4, tx = tid & 15;
  const int row0 = blockIdx.x * 128;

  float acc[8][3];
#pragma unroll
  for (int i = 0; i < 8; i++)
#pragma unroll
    for (int j = 0; j < 3; j++) acc[i][j] = 0.0f;

  for (int kt = 0; kt < KD; kt += 16) {
    // x tile: 128 rows x 16 k (512 float4), transposed into As[k][row]
#pragma unroll
    for (int l = 0; l < 2; l++) {
      int idx = tid + l * 256;
      int r = idx >> 2, kq = (idx & 3) * 4;
      float4 v = *reinterpret_cast<const float4*>(
          x + (size_t)(row0 + r) * KD + kt + kq);
      As[kq + 0][r] = v.x; As[kq + 1][r] = v.y;
      As[kq + 2][r] = v.z; As[kq + 3][r] = v.w;
    }
    // w tile: 48 x 16 (192 float4) into Ws[k][nf]
    if (tid < 192) {
      int nf = tid >> 2, kq = (tid & 3) * 4;
      float4 v = *reinterpret_cast<const float4*>(
          w1 + (size_t)nf * KD + kt + kq);
      Ws[kq + 0][nf] = v.x; Ws[kq + 1][nf] = v.y;
      Ws[kq + 2][nf] = v.z; Ws[kq + 3][nf] = v.w;
    }
    __syncthreads();
#pragma unroll
    for (int k = 0; k < 16; k++) {
      float4 a03 = *reinterpret_cast<const float4*>(&As[k][ty * 8 + 0]);
      float4 a47 = *reinterpret_cast<const float4*>(&As[k][ty * 8 + 4]);
      float wv0 = Ws[k][tx * 3 + 0];
      float wv1 = Ws[k][tx * 3 + 1];
      float wv2 = Ws[k][tx * 3 + 2];
      acc[0][0] = fmaf(a03.x, wv0, acc[0][0]);
      acc[0][1] = fmaf(a03.x, wv1, acc[0][1]);
      acc[0][2] = fmaf(a03.x, wv2, acc[0][2]);
      acc[1][0] = fmaf(a03.y, wv0, acc[1][0]);
      acc[1][1] = fmaf(a03.y, wv1, acc[1][1]);
      acc[1][2] = fmaf(a03.y, wv2, acc[1][2]);
      acc[2][0] = fmaf(a03.z, wv0, acc[2][0]);
      acc[2][1] = fmaf(a03.z, wv1, acc[2][1]);
      acc[2][2] = fmaf(a03.z, wv2, acc[2][2]);
      acc[3][0] = fmaf(a03.w, wv0, acc[3][0]);
      acc[3][1] = fmaf(a03.w, wv1, acc[3][1]);
      acc[3][2] = fmaf(a03.w, wv2, acc[3][2]);
      acc[4][0] = fmaf(a47.x, wv0, acc[4][0]);
      acc[4][1] = fmaf(a47.x, wv1, acc[4][1]);
      acc[4][2] = fmaf(a47.x, wv2, acc[4][2]);
      acc[5][0] = fmaf(a47.y, wv0, acc[5][0]);
      acc[5][1] = fmaf(a47.y, wv1, acc[5][1]);
      acc[5][2] = fmaf(a47.y, wv2, acc[5][2]);
      acc[6][0] = fmaf(a47.z, wv0, acc[6][0]);
      acc[6][1] = fmaf(a47.z, wv1, acc[6][1]);
      acc[6][2] = fmaf(a47.z, wv2, acc[6][2]);
      acc[7][0] = fmaf(a47.w, wv0, acc[7][0]);
      acc[7][1] = fmaf(a47.w, wv1, acc[7][1]);
      acc[7][2] = fmaf(a47.w, wv2, acc[7][2]);
    }
    __syncthreads();
  }

  // epilogue: add bias, store y1, reduce per-column sum/sumsq
  float bias[3], cs[3] = {0.f, 0.f, 0.f}, css[3] = {0.f, 0.f, 0.f};
#pragma unroll
  for (int j = 0; j < 3; j++) bias[j] = b1[tx * 3 + j];
#pragma unroll
  for (int i = 0; i < 8; i++) {
#pragma unroll
    for (int j = 0; j < 3; j++) {
      float y = acc[i][j] + bias[j];
      int r = ty * 8 + i;
      g_y1[(size_t)(row0 + r) * F1 + tx * 3 + j] = y;
      cs[j] += y;
      css[j] += y * y;
    }
  }
#pragma unroll
  for (int j = 0; j < 3; j++) red[tx * 3 + j][ty] = make_float2(cs[j], css[j]);
  __syncthreads();
  if (tid < F1) {
    float s = 0.f, ss = 0.f;
#pragma unroll
    for (int t = 0; t < 16; t++) { s += red[tid][t].x; ss += red[tid][t].y; }
    g_part1[blockIdx.x][tid][0] = s;
    g_part1[blockIdx.x][tid][1] = ss;
  }
}

// ---------------- finalize: BN params + analytic global mean/std*u ----------
__global__ void finalize_kernel(int layer, const float* __restrict__ gamma,
                                const float* __restrict__ beta, float uval) {
  const int F = (layer == 1) ? F1 : F2;
  const float* base = (layer == 1) ? &g_part1[0][0][0] : &g_part2[0][0][0];
  __shared__ float contrib[F1], betas[F1];
  int f = threadIdx.x;
  if (f < F) {
    float s0 = 0, s1 = 0, s2 = 0, s3 = 0, q0 = 0, q1 = 0, q2 = 0, q3 = 0;
    for (int b = 0; b < NBLK; b += 4) {
      const float* p0 = base + ((size_t)(b + 0) * F + f) * 2;
      const float* p1 = base + ((size_t)(b + 1) * F + f) * 2;
      const float* p2 = base + ((size_t)(b + 2) * F + f) * 2;
      const float* p3 = base + ((size_t)(b + 3) * F + f) * 2;
      s0 += p0[0]; q0 += p0[1];
      s1 += p1[0]; q1 += p1[1];
      s2 += p2[0]; q2 += p2[1];
      s3 += p3[0]; q3 += p3[1];
    }
    double s = (double)s0 + s1 + s2 + s3;
    double ss = (double)q0 + q1 + q2 + q3;
    double mean = s / 65536.0;
    double var = ss / 65536.0 - mean * mean;
    double rr = 1.0 / sqrt(var + 1e-5);
    double g = (double)gamma[f];
    if (layer == 1) {
      g_sc1[f] = (float)(g * rr);
      g_sh1[f] = (float)((double)beta[f] - mean * g * rr);
    } else {
      g_sc2[f] = (float)(g * rr);
      g_sh2[f] = (float)((double)beta[f] - mean * g * rr);
    }
    contrib[f] = (float)(g * g * var / (var + 1e-5));
    betas[f] = beta[f];
  }
  __syncthreads();
  if (f == 0) {
    float bm = 0.f;
    for (int i = 0; i < F; i++) bm += betas[i];
    bm /= (float)F;
    double acc = 0.0;
    for (int i = 0; i < F; i++) {
      double d = (double)betas[i] - bm;
      acc += (double)contrib[i] + d * d;
    }
    double ntot = 65536.0 * (double)F;
    double s2 = 65536.0 * acc / (ntot - 1.0);
    float* msu = (layer == 1) ? g_msu1 : g_msu2;
    msu[0] = bm;                       // global mean of BN output (= mean(beta))
    msu[1] = (float)sqrt(s2) * uval;   // std(ddof=1) * U(1,2)
  }
}

// ---------------- K3: BN1 + noise + relu + GEMM2 + partial stats ------------
__global__ __launch_bounds__(128) void layer2_kernel(const float* __restrict__ w2,
                                                     const float* __restrict__ b2,
                                                     uint32_t kn0, uint32_t kn1) {
  __shared__ __align__(16) float ys[128][49];   // padded: conflict-free row reads
  __shared__ __align__(16) float w2s[F2][F1];
  __shared__ float b2s[F2];
  __shared__ float sc[F1], sh[F1];
  __shared__ __align__(16) float outs[128][F2];

  const int tid = threadIdx.x;
  const int row0 = blockIdx.x * 128;

  const float4* src = reinterpret_cast<const float4*>(g_y1 + (size_t)row0 * F1);
#pragma unroll
  for (int l = 0; l < 12; l++) {
    int idx = tid + l * 128;              // 1536 float4
    float4 v = src[idx];
    int fi = idx * 4, r = fi / F1, c = fi % F1;
    ys[r][c] = v.x; ys[r][c + 1] = v.y; ys[r][c + 2] = v.z; ys[r][c + 3] = v.w;
  }
#pragma unroll
  for (int l = 0; l < 3; l++) {
    int idx = tid + l * 128;
    if (idx < (F2 * F1) / 4) {
      float4 v = reinterpret_cast<const float4*>(w2)[idx];
      float* dst = &w2s[0][0] + idx * 4;
      dst[0] = v.x; dst[1] = v.y; dst[2] = v.z; dst[3] = v.w;
    }
  }
  if (tid < F2) b2s[tid] = b2[tid];
  if (tid < F1) { sc[tid] = g_sc1[tid]; sh[tid] = g_sh1[tid]; }
  const float m1 = g_msu1[0], su1 = g_msu1[1];
  __syncthreads();

  const int grow = row0 + tid;
  const uint32_t ebase = (uint32_t)grow * (uint32_t)F1;
  float acc[F2];
#pragma unroll
  for (int j = 0; j < F2; j++) acc[j] = b2s[j];

  for (int c = 0; c < F1; c++) {
    float z = fmaf(ys[tid][c], sc[c], sh[c]);
    uint32_t bits = jax_bits32(kn0, kn1, ebase + (uint32_t)c);
    float h = fmaxf(z + fmaf(su1, jax_normal(bits), m1), 0.0f);
#pragma unroll
    for (int j = 0; j < F2; j++) acc[j] = fmaf(h, w2s[j][c], acc[j]);
  }
#pragma unroll
  for (int j = 0; j < F2; j++) outs[tid][j] = acc[j];
  __syncthreads();

  if (tid < F2) {
    float s = 0.f, ss = 0.f;
    for (int r = 0; r < 128; r++) {
      float v = outs[r][tid];
      s += v; ss += v * v;
    }
    g_part2[blockIdx.x][tid][0] = s;
    g_part2[blockIdx.x][tid][1] = ss;
  }
  float4* dst = reinterpret_cast<float4*>(g_y2 + (size_t)row0 * F2);
  const float4* osrc = reinterpret_cast<const float4*>(&outs[0][0]);
#pragma unroll
  for (int l = 0; l < 6; l++) dst[tid + l * 128] = osrc[tid + l * 128];
}

// ---------------- K5: BN2 + noise + relu + GEMM3 -> out ---------------------
__global__ __launch_bounds__(128) void layer3_kernel(const float* __restrict__ w3,
                                                     const float* __restrict__ b3,
                                                     float* __restrict__ out,
                                                     uint32_t kn0, uint32_t kn1) {
  __shared__ __align__(16) float ys[128][25];
  __shared__ float w3s[F3][F2];
  __shared__ float b3s[F3];
  __shared__ float sc[F2], sh[F2];
  __shared__ __align__(16) float outs[128][F3];

  const int tid = threadIdx.x;
  const int row0 = blockIdx.x * 128;

  const float4* src = reinterpret_cast<const float4*>(g_y2 + (size_t)row0 * F2);
#pragma unroll
  for (int l = 0; l < 6; l++) {
    int idx = tid + l * 128;              // 768 float4
    float4 v = src[idx];
    int fi = idx * 4, r = fi / F2, c = fi % F2;
    ys[r][c] = v.x; ys[r][c + 1] = v.y; ys[r][c + 2] = v.z; ys[r][c + 3] = v.w;
  }
  // w3 has F3*F2 = 240 elements but only 128 threads: TWO iterations.
  // (Round<=3 bug: single `if (tid < 240)` left w3s[128..239] uninitialized.)
#pragma unroll
  for (int l = 0; l < 2; l++) {
    int idx = tid + l * 128;
    if (idx < F3 * F2) (&w3s[0][0])[idx] = w3[idx];
  }
  if (tid < F3) b3s[tid] = b3[tid];
  if (tid < F2) { sc[tid] = g_sc2[tid]; sh[tid] = g_sh2[tid]; }
  const float m2 = g_msu2[0], su2 = g_msu2[1];
  __syncthreads();

  const int grow = row0 + tid;
  const uint32_t ebase = (uint32_t)grow * (uint32_t)F2;
  float acc[F3];
#pragma unroll
  for (int j = 0; j < F3; j++) acc[j] = b3s[j];

  for (int c = 0; c < F2; c++) {
    float z = fmaf(ys[tid][c], sc[c], sh[c]);
    uint32_t bits = jax_bits32(kn0, kn1, ebase + (uint32_t)c);
    float h = fmaxf(z + fmaf(su2, jax_normal(bits), m2), 0.0f);
#pragma unroll
    for (int j = 0; j < F3; j++) acc[j] = fmaf(h, w3s[j][c], acc[j]);
  }
#pragma unroll
  for (int j = 0; j < F3; j++) outs[tid][j] = acc[j];
  __syncthreads();

  float* dst = out + (size_t)row0 * F3;
  const float* osrc = &outs[0][0];
#pragma unroll
  for (int l = 0; l < F3; l++) dst[tid + l * 128] = osrc[tid + l * 128];
}

// ---------------- host: derive JAX subkeys + uniform scalars ----------------
// JAX >= 0.4.36: jax_threefry_partitionable defaults to True.
//   split(key)[i]   = full output pair of threefry(key, (0, i))
//   bits32(key, e)  = out0 ^ out1 of threefry(key, (0, e))
static void derive_keys(uint32_t seed, uint32_t& kn0, uint32_t& kn1, float& uval) {
  uint32_t k0 = 0u, k1 = seed;
  uint32_t a0, a1, b0, b1;
  tf2x32(k0, k1, 0u, 0u, a0, a1);   // subkey 0 = ku
  tf2x32(k0, k1, 0u, 1u, b0, b1);   // subkey 1 = kn
  kn0 = b0; kn1 = b1;
  uint32_t u0, u1;
  tf2x32(a0, a1, 0u, 0u, u0, u1);   // random_bits(ku, shape=())
  uint32_t bits = u0 ^ u1;
  uint32_t fb = (bits >> 9) | 0x3f800000u;
  float f;
  memcpy(&f, &fb, sizeof(float));
  uval = f;   // uniform(ku, (), minval=1, maxval=2) = [1,2) mantissa draw
}

extern "C" void kernel_launch(void* const* d_in, const int* in_sizes, int n_in,
                              void* d_out, int out_size) {
  const float* x      = (const float*)d_in[0];
  const float* w1     = (const float*)d_in[1];
  const float* b1     = (const float*)d_in[2];
  const float* gamma1 = (const float*)d_in[3];
  const float* beta1  = (const float*)d_in[4];
  const float* w2     = (const float*)d_in[5];
  const float* b2     = (const float*)d_in[6];
  const float* gamma2 = (const float*)d_in[7];
  const float* beta2  = (const float*)d_in[8];
  const float* w3     = (const float*)d_in[9];
  const float* b3     = (const float*)d_in[10];
  float* out = (float*)d_out;

  uint32_t kn10, kn11, kn20, kn21;
  float u1, u2;
  derive_keys(1234u, kn10, kn11, u1);
  derive_keys(5678u, kn20, kn21, u2);

  gemm1_kernel<<<NBLK, 256>>>(x, w1, b1);
  finalize_kernel<<<1, 64>>>(1, gamma1, beta1, u1);
  layer2_kernel<<<NBLK, 128>>>(w2, b2, kn10, kn11);
  finalize_kernel<<<1, 64>>>(2, gamma2, beta2, u2);
  layer3_kernel<<<NBLK, 128>>>(w3, b3, out, kn20, kn21);
}

// round 9
// speedup vs baseline: 1.0140x; 1.0112x over previous
#include <cuda_runtime.h>
#include <cstdint>
#include <cstring>

// Problem constants
#define BATCH 65536
#define KD    784
#define F1    48
#define F2    24
#define F3    10
#define NBLK  512           // BATCH / 128

// ---------------- scratch (device globals; no allocations allowed) ----------
__device__ __align__(16) float g_y1[BATCH * F1];
__device__ __align__(16) float g_y2[BATCH * F2];
__device__ float g_part1[NBLK][F1][2];
__device__ float g_part2[NBLK][F2][2];
__device__ float g_sc1[F1], g_sh1[F1], g_msu1[2];
__device__ float g_sc2[F2], g_sh2[F2], g_msu2[2];

// ---------------- Threefry2x32 (bit-exact JAX) ------------------------------
__host__ __device__ __forceinline__ void tf2x32(uint32_t k0, uint32_t k1,
                                                uint32_t x0, uint32_t x1,
                                                uint32_t& o0, uint32_t& o1) {
  uint32_t ks2 = k0 ^ k1 ^ 0x1BD11BDAu;
  x0 += k0; x1 += k1;
#define TFR(r) { x0 += x1; x1 = (x1 << (r)) | (x1 >> (32 - (r))); x1 ^= x0; }
  TFR(13) TFR(15) TFR(26) TFR(6)
  x0 += k1;  x1 += ks2 + 1u;
  TFR(17) TFR(29) TFR(16) TFR(24)
  x0 += ks2; x1 += k0 + 2u;
  TFR(13) TFR(15) TFR(26) TFR(6)
  x0 += k0;  x1 += k1 + 3u;
  TFR(17) TFR(29) TFR(16) TFR(24)
  x0 += k1;  x1 += ks2 + 4u;
  TFR(13) TFR(15) TFR(26) TFR(6)
  x0 += ks2; x1 += k0 + 5u;
#undef TFR
  o0 = x0; o1 = x1;
}

// JAX partitionable random_bits for 32-bit, element index e (< 2^32):
// counts = (hi64(e)=0, lo64(e)=e); bits = out0 ^ out1.
__device__ __forceinline__ uint32_t jax_bits32(uint32_t k0, uint32_t k1,
                                               uint32_t e) {
  uint32_t o0, o1;
  tf2x32(k0, k1, 0u, e, o0, o1);
  return o0 ^ o1;
}

// XLA/Giles single-precision erfinv (matches jax.lax.erf_inv f32 path)
__device__ __forceinline__ float jax_erfinv(float x) {
  float w = -log1pf(-x * x);
  float p;
  if (w < 5.0f) {
    w -= 2.5f;
    p = 2.81022636e-08f;
    p = fmaf(p, w, 3.43273939e-07f);
    p = fmaf(p, w, -3.5233877e-06f);
    p = fmaf(p, w, -4.39150654e-06f);
    p = fmaf(p, w, 0.00021858087f);
    p = fmaf(p, w, -0.00125372503f);
    p = fmaf(p, w, -0.00417768164f);
    p = fmaf(p, w, 0.246640727f);
    p = fmaf(p, w, 1.50140941f);
  } else {
    w = sqrtf(w) - 3.0f;
    p = -0.000200214257f;
    p = fmaf(p, w, 0.000100950558f);
    p = fmaf(p, w, 0.00134934322f);
    p = fmaf(p, w, -0.00367342844f);
    p = fmaf(p, w, 0.00573950773f);
    p = fmaf(p, w, -0.0076224613f);
    p = fmaf(p, w, 0.00943887047f);
    p = fmaf(p, w, 1.00167406f);
    p = fmaf(p, w, 2.83297682f);
  }
  return p * x;
}

// jax.random.normal from one 32-bit draw: sqrt(2)*erfinv(uniform(lo=-1+ulp, 1))
__device__ __forceinline__ float jax_normal(uint32_t bits) {
  float u = __uint_as_float((bits >> 9) | 0x3f800000u) - 1.0f;  // [0,1)
  float r = fmaf(u, 2.0f, -0.99999994f);   // (hi-lo) rounds to 2.0f in f32
  r = fmaxf(-0.99999994f, r);
  return 1.41421356f * jax_erfinv(r);
}

// ---------------- K1: GEMM1 (x @ w1^T + b1) + per-feature partial stats -----
// BM=128 rows/block, BN=48 (full), BK=16. 256 threads: 16x16, each 8 rows x 3 cols.
__global__ __launch_bounds__(256) void gemm1_kernel(const float* __restrict__ x,
                                                    const float* __restrict__ w1,
                                                    const float* __restrict__ b1) {
  __shared__ __align__(16) float As[16][128];
  __shared__ __align__(16) float Ws[16][F1];
  __shared__ float2 red[F1][16];

  const int tid = threadIdx.x;
  const int ty = tid >> 4, tx = tid & 15;
  const int row0 = blockIdx.x * 128;

  float acc[8][3];
#pragma unroll
  for (int i = 0; i < 8; i++)
#pragma unroll
    for (int j = 0; j < 3; j++) acc[i][j] = 0.0f;

  for (int kt = 0; kt < KD; kt += 16) {
    // x tile: 128 rows x 16 k (512 float4), transposed into As[k][row]
#pragma unroll
    for (int l = 0; l < 2; l++) {
      int idx = tid + l * 256;
      int r = idx >> 2, kq = (idx & 3) * 4;
      float4 v = *reinterpret_cast<const float4*>(
          x + (size_t)(row0 + r) * KD + kt + kq);
      As[kq + 0][r] = v.x; As[kq + 1][r] = v.y;
      As[kq + 2][r] = v.z; As[kq + 3][r] = v.w;
    }
    // w tile: 48 x 16 (192 float4) into Ws[k][nf]
    if (tid < 192) {
      int nf = tid >> 2, kq = (tid & 3) * 4;
      float4 v = *reinterpret_cast<const float4*>(
          w1 + (size_t)nf * KD + kt + kq);
      Ws[kq + 0][nf] = v.x; Ws[kq + 1][nf] = v.y;
      Ws[kq + 2][nf] = v.z; Ws[kq + 3][nf] = v.w;
    }
    __syncthreads();
#pragma unroll
    for (int k = 0; k < 16; k++) {
      float4 a03 = *reinterpret_cast<const float4*>(&As[k][ty * 8 + 0]);
      float4 a47 = *reinterpret_cast<const float4*>(&As[k][ty * 8 + 4]);
      float wv0 = Ws[k][tx * 3 + 0];
      float wv1 = Ws[k][tx * 3 + 1];
      float wv2 = Ws[k][tx * 3 + 2];
      acc[0][0] = fmaf(a03.x, wv0, acc[0][0]);
      acc[0][1] = fmaf(a03.x, wv1, acc[0][1]);
      acc[0][2] = fmaf(a03.x, wv2, acc[0][2]);
      acc[1][0] = fmaf(a03.y, wv0, acc[1][0]);
      acc[1][1] = fmaf(a03.y, wv1, acc[1][1]);
      acc[1][2] = fmaf(a03.y, wv2, acc[1][2]);
      acc[2][0] = fmaf(a03.z, wv0, acc[2][0]);
      acc[2][1] = fmaf(a03.z, wv1, acc[2][1]);
      acc[2][2] = fmaf(a03.z, wv2, acc[2][2]);
      acc[3][0] = fmaf(a03.w, wv0, acc[3][0]);
      acc[3][1] = fmaf(a03.w, wv1, acc[3][1]);
      acc[3][2] = fmaf(a03.w, wv2, acc[3][2]);
      acc[4][0] = fmaf(a47.x, wv0, acc[4][0]);
      acc[4][1] = fmaf(a47.x, wv1, acc[4][1]);
      acc[4][2] = fmaf(a47.x, wv2, acc[4][2]);
      acc[5][0] = fmaf(a47.y, wv0, acc[5][0]);
      acc[5][1] = fmaf(a47.y, wv1, acc[5][1]);
      acc[5][2] = fmaf(a47.y, wv2, acc[5][2]);
      acc[6][0] = fmaf(a47.z, wv0, acc[6][0]);
      acc[6][1] = fmaf(a47.z, wv1, acc[6][1]);
      acc[6][2] = fmaf(a47.z, wv2, acc[6][2]);
      acc[7][0] = fmaf(a47.w, wv0, acc[7][0]);
      acc[7][1] = fmaf(a47.w, wv1, acc[7][1]);
      acc[7][2] = fmaf(a47.w, wv2, acc[7][2]);
    }
    __syncthreads();
  }

  // epilogue: add bias, store y1, reduce per-column sum/sumsq
  float bias[3], cs[3] = {0.f, 0.f, 0.f}, css[3] = {0.f, 0.f, 0.f};
#pragma unroll
  for (int j = 0; j < 3; j++) bias[j] = b1[tx * 3 + j];
#pragma unroll
  for (int i = 0; i < 8; i++) {
#pragma unroll
    for (int j = 0; j < 3; j++) {
      float y = acc[i][j] + bias[j];
      int r = ty * 8 + i;
      g_y1[(size_t)(row0 + r) * F1 + tx * 3 + j] = y;
      cs[j] += y;
      css[j] += y * y;
    }
  }
#pragma unroll
  for (int j = 0; j < 3; j++) red[tx * 3 + j][ty] = make_float2(cs[j], css[j]);
  __syncthreads();
  if (tid < F1) {
    float s = 0.f, ss = 0.f;
#pragma unroll
    for (int t = 0; t < 16; t++) { s += red[tid][t].x; ss += red[tid][t].y; }
    g_part1[blockIdx.x][tid][0] = s;
    g_part1[blockIdx.x][tid][1] = ss;
  }
}

// ---------------- finalize: BN params + analytic global mean/std*u ----------
__global__ void finalize_kernel(int layer, const float* __restrict__ gamma,
                                const float* __restrict__ beta, float uval) {
  const int F = (layer == 1) ? F1 : F2;
  const float* base = (layer == 1) ? &g_part1[0][0][0] : &g_part2[0][0][0];
  __shared__ float contrib[F1], betas[F1];
  int f = threadIdx.x;
  if (f < F) {
    float s0 = 0, s1 = 0, s2 = 0, s3 = 0, q0 = 0, q1 = 0, q2 = 0, q3 = 0;
    for (int b = 0; b < NBLK; b += 4) {
      const float* p0 = base + ((size_t)(b + 0) * F + f) * 2;
      const float* p1 = base + ((size_t)(b + 1) * F + f) * 2;
      const float* p2 = base + ((size_t)(b + 2) * F + f) * 2;
      const float* p3 = base + ((size_t)(b + 3) * F + f) * 2;
      s0 += p0[0]; q0 += p0[1];
      s1 += p1[0]; q1 += p1[1];
      s2 += p2[0]; q2 += p2[1];
      s3 += p3[0]; q3 += p3[1];
    }
    double s = (double)s0 + s1 + s2 + s3;
    double ss = (double)q0 + q1 + q2 + q3;
    double mean = s / 65536.0;
    double var = ss / 65536.0 - mean * mean;
    double rr = 1.0 / sqrt(var + 1e-5);
    double g = (double)gamma[f];
    if (layer == 1) {
      g_sc1[f] = (float)(g * rr);
      g_sh1[f] = (float)((double)beta[f] - mean * g * rr);
    } else {
      g_sc2[f] = (float)(g * rr);
      g_sh2[f] = (float)((double)beta[f] - mean * g * rr);
    }
    contrib[f] = (float)(g * g * var / (var + 1e-5));
    betas[f] = beta[f];
  }
  __syncthreads();
  if (f == 0) {
    float bm = 0.f;
    for (int i = 0; i < F; i++) bm += betas[i];
    bm /= (float)F;
    double acc = 0.0;
    for (int i = 0; i < F; i++) {
      double d = (double)betas[i] - bm;
      acc += (double)contrib[i] + d * d;
    }
    double ntot = 65536.0 * (double)F;
    double s2 = 65536.0 * acc / (ntot - 1.0);
    float* msu = (layer == 1) ? g_msu1 : g_msu2;
    msu[0] = bm;                       // global mean of BN output (= mean(beta))
    msu[1] = (float)sqrt(s2) * uval;   // std(ddof=1) * U(1,2)
  }
}

// ---------------- K3: BN1 + noise + relu + GEMM2 + partial stats ------------
__global__ __launch_bounds__(128) void layer2_kernel(const float* __restrict__ w2,
                                                     const float* __restrict__ b2,
                                                     uint32_t kn0, uint32_t kn1) {
  __shared__ __align__(16) float ys[128][49];   // padded: conflict-free row reads
  __shared__ __align__(16) float w2s[F2][F1];
  __shared__ float b2s[F2];
  __shared__ float sc[F1], sh[F1];
  __shared__ __align__(16) float outs[128][F2];

  const int tid = threadIdx.x;
  const int row0 = blockIdx.x * 128;

  const float4* src = reinterpret_cast<const float4*>(g_y1 + (size_t)row0 * F1);
#pragma unroll
  for (int l = 0; l < 12; l++) {
    int idx = tid + l * 128;              // 1536 float4
    float4 v = src[idx];
    int fi = idx * 4, r = fi / F1, c = fi % F1;
    ys[r][c] = v.x; ys[r][c + 1] = v.y; ys[r][c + 2] = v.z; ys[r][c + 3] = v.w;
  }
#pragma unroll
  for (int l = 0; l < 3; l++) {
    int idx = tid + l * 128;
    if (idx < (F2 * F1) / 4) {
      float4 v = reinterpret_cast<const float4*>(w2)[idx];
      float* dst = &w2s[0][0] + idx * 4;
      dst[0] = v.x; dst[1] = v.y; dst[2] = v.z; dst[3] = v.w;
    }
  }
  if (tid < F2) b2s[tid] = b2[tid];
  if (tid < F1) { sc[tid] = g_sc1[tid]; sh[tid] = g_sh1[tid]; }
  const float m1 = g_msu1[0], su1 = g_msu1[1];
  __syncthreads();

  const int grow = row0 + tid;
  const uint32_t ebase = (uint32_t)grow * (uint32_t)F1;
  float acc[F2];
#pragma unroll
  for (int j = 0; j < F2; j++) acc[j] = b2s[j];

  for (int c = 0; c < F1; c++) {
    float z = fmaf(ys[tid][c], sc[c], sh[c]);
    uint32_t bits = jax_bits32(kn0, kn1, ebase + (uint32_t)c);
    float h = fmaxf(z + fmaf(su1, jax_normal(bits), m1), 0.0f);
#pragma unroll
    for (int j = 0; j < F2; j++) acc[j] = fmaf(h, w2s[j][c], acc[j]);
  }
#pragma unroll
  for (int j = 0; j < F2; j++) outs[tid][j] = acc[j];
  __syncthreads();

  if (tid < F2) {
    float s = 0.f, ss = 0.f;
    for (int r = 0; r < 128; r++) {
      float v = outs[r][tid];
      s += v; ss += v * v;
    }
    g_part2[blockIdx.x][tid][0] = s;
    g_part2[blockIdx.x][tid][1] = ss;
  }
  float4* dst = reinterpret_cast<float4*>(g_y2 + (size_t)row0 * F2);
  const float4* osrc = reinterpret_cast<const float4*>(&outs[0][0]);
#pragma unroll
  for (int l = 0; l < 6; l++) dst[tid + l * 128] = osrc[tid + l * 128];
}

// ---------------- K5: BN2 + noise + relu + GEMM3 -> out ---------------------
__global__ __launch_bounds__(128) void layer3_kernel(const float* __restrict__ w3,
                                                     const float* __restrict__ b3,
                                                     float* __restrict__ out,
                                                     uint32_t kn0, uint32_t kn1) {
  __shared__ __align__(16) float ys[128][25];
  __shared__ float w3s[F3][F2];
  __shared__ float b3s[F3];
  __shared__ float sc[F2], sh[F2];
  __shared__ __align__(16) float outs[128][F3];

  const int tid = threadIdx.x;
  const int row0 = blockIdx.x * 128;

  const float4* src = reinterpret_cast<const float4*>(g_y2 + (size_t)row0 * F2);
#pragma unroll
  for (int l = 0; l < 6; l++) {
    int idx = tid + l * 128;              // 768 float4
    float4 v = src[idx];
    int fi = idx * 4, r = fi / F2, c = fi % F2;
    ys[r][c] = v.x; ys[r][c + 1] = v.y; ys[r][c + 2] = v.z; ys[r][c + 3] = v.w;
  }
  // w3 has F3*F2 = 240 elements but only 128 threads: TWO iterations.
  // (Round<=3 bug: single `if (tid < 240)` left w3s[128..239] uninitialized.)
#pragma unroll
  for (int l = 0; l < 2; l++) {
    int idx = tid + l * 128;
    if (idx < F3 * F2) (&w3s[0][0])[idx] = w3[idx];
  }
  if (tid < F3) b3s[tid] = b3[tid];
  if (tid < F2) { sc[tid] = g_sc2[tid]; sh[tid] = g_sh2[tid]; }
  const float m2 = g_msu2[0], su2 = g_msu2[1];
  __syncthreads();

  const int grow = row0 + tid;
  const uint32_t ebase = (uint32_t)grow * (uint32_t)F2;
  float acc[F3];
#pragma unroll
  for (int j = 0; j < F3; j++) acc[j] = b3s[j];

  for (int c = 0; c < F2; c++) {
    float z = fmaf(ys[tid][c], sc[c], sh[c]);
    uint32_t bits = jax_bits32(kn0, kn1, ebase + (uint32_t)c);
    float h = fmaxf(z + fmaf(su2, jax_normal(bits), m2), 0.0f);
#pragma unroll
    for (int j = 0; j < F3; j++) acc[j] = fmaf(h, w3s[j][c], acc[j]);
  }
#pragma unroll
  for (int j = 0; j < F3; j++) outs[tid][j] = acc[j];
  __syncthreads();

  float* dst = out + (size_t)row0 * F3;
  const float* osrc = &outs[0][0];
#pragma unroll
  for (int l = 0; l < F3; l++) dst[tid + l * 128] = osrc[tid + l * 128];
}

// ---------------- host: derive JAX subkeys + uniform scalars ----------------
// JAX >= 0.4.36: jax_threefry_partitionable defaults to True.
//   split(key)[i]   = full output pair of threefry(key, (0, i))
//   bits32(key, e)  = out0 ^ out1 of threefry(key, (0, e))
static void derive_keys(uint32_t seed, uint32_t& kn0, uint32_t& kn1, float& uval) {
  uint32_t k0 = 0u, k1 = seed;
  uint32_t a0, a1, b0, b1;
  tf2x32(k0, k1, 0u, 0u, a0, a1);   // subkey 0 = ku
  tf2x32(k0, k1, 0u, 1u, b0, b1);   // subkey 1 = kn
  kn0 = b0; kn1 = b1;
  uint32_t u0, u1;
  tf2x32(a0, a1, 0u, 0u, u0, u1);   // random_bits(ku, shape=())
  uint32_t bits = u0 ^ u1;
  uint32_t fb = (bits >> 9) | 0x3f800000u;
  float f;
  memcpy(&f, &fb, sizeof(float));
  uval = f;   // uniform(ku, (), minval=1, maxval=2) = [1,2) mantissa draw
}

extern "C" void kernel_launch(void* const* d_in, const int* in_sizes, int n_in,
                              void* d_out, int out_size) {
  const float* x      = (const float*)d_in[0];
  const float* w1     = (const float*)d_in[1];
  const float* b1     = (const float*)d_in[2];
  const float* gamma1 = (const float*)d_in[3];
  const float* beta1  = (const float*)d_in[4];
  const float* w2     = (const float*)d_in[5];
  const float* b2     = (const float*)d_in[6];
  const float* gamma2 = (const float*)d_in[7];
  const float* beta2  = (const float*)d_in[8];
  const float* w3     = (const float*)d_in[9];
  const float* b3     = (const float*)d_in[10];
  float* out = (float*)d_out;

  uint32_t kn10, kn11, kn20, kn21;
  float u1, u2;
  derive_keys(1234u, kn10, kn11, u1);
  derive_keys(5678u, kn20, kn21, u2);

  gemm1_kernel<<<NBLK, 256>>>(x, w1, b1);
  finalize_kernel<<<1, 64>>>(1, gamma1, beta1, u1);
  layer2_kernel<<<NBLK, 128>>>(w2, b2, kn10, kn11);
  finalize_kernel<<<1, 64>>>(2, gamma2, beta2, u2);
  layer3_kernel<<<NBLK, 128>>>(w3, b3, out, kn20, kn21);
}

// round 10
// speedup vs baseline: 1.0187x; 1.0046x over previous
#include <cuda_runtime.h>
#include <cstdint>
#include <cstring>

// Problem constants
#define BATCH 65536
#define KD    784
#define F1    48
#define F2    24
#define F3    10
#define NBLK  512           // BATCH / 128

// ---------------- scratch (device globals; no allocations allowed) ----------
__device__ __align__(16) float g_y1[BATCH * F1];
__device__ __align__(16) float g_y2[BATCH * F2];
__device__ float g_part1[NBLK][F1][2];
__device__ float g_part2[NBLK][F2][2];
__device__ float g_sc1[F1], g_sh1[F1], g_msu1[2];
__device__ float g_sc2[F2], g_sh2[F2], g_msu2[2];

// ---------------- Threefry2x32 (bit-exact JAX) ------------------------------
__host__ __device__ __forceinline__ void tf2x32(uint32_t k0, uint32_t k1,
                                                uint32_t x0, uint32_t x1,
                                                uint32_t& o0, uint32_t& o1) {
  uint32_t ks2 = k0 ^ k1 ^ 0x1BD11BDAu;
  x0 += k0; x1 += k1;
#define TFR(r) { x0 += x1; x1 = (x1 << (r)) | (x1 >> (32 - (r))); x1 ^= x0; }
  TFR(13) TFR(15) TFR(26) TFR(6)
  x0 += k1;  x1 += ks2 + 1u;
  TFR(17) TFR(29) TFR(16) TFR(24)
  x0 += ks2; x1 += k0 + 2u;
  TFR(13) TFR(15) TFR(26) TFR(6)
  x0 += k0;  x1 += k1 + 3u;
  TFR(17) TFR(29) TFR(16) TFR(24)
  x0 += k1;  x1 += ks2 + 4u;
  TFR(13) TFR(15) TFR(26) TFR(6)
  x0 += ks2; x1 += k0 + 5u;
#undef TFR
  o0 = x0; o1 = x1;
}

// JAX partitionable random_bits for 32-bit, element index e (< 2^32):
// counts = (hi64(e)=0, lo64(e)=e); bits = out0 ^ out1.
__device__ __forceinline__ uint32_t jax_bits32(uint32_t k0, uint32_t k1,
                                               uint32_t e) {
  uint32_t o0, o1;
  tf2x32(k0, k1, 0u, e, o0, o1);
  return o0 ^ o1;
}

// XLA/Giles single-precision erfinv (matches jax.lax.erf_inv f32 path)
__device__ __forceinline__ float jax_erfinv(float x) {
  float w = -log1pf(-x * x);
  float p;
  if (w < 5.0f) {
    w -= 2.5f;
    p = 2.81022636e-08f;
    p = fmaf(p, w, 3.43273939e-07f);
    p = fmaf(p, w, -3.5233877e-06f);
    p = fmaf(p, w, -4.39150654e-06f);
    p = fmaf(p, w, 0.00021858087f);
    p = fmaf(p, w, -0.00125372503f);
    p = fmaf(p, w, -0.00417768164f);
    p = fmaf(p, w, 0.246640727f);
    p = fmaf(p, w, 1.50140941f);
  } else {
    w = sqrtf(w) - 3.0f;
    p = -0.000200214257f;
    p = fmaf(p, w, 0.000100950558f);
    p = fmaf(p, w, 0.00134934322f);
    p = fmaf(p, w, -0.00367342844f);
    p = fmaf(p, w, 0.00573950773f);
    p = fmaf(p, w, -0.0076224613f);
    p = fmaf(p, w, 0.00943887047f);
    p = fmaf(p, w, 1.00167406f);
    p = fmaf(p, w, 2.83297682f);
  }
  return p * x;
}

// jax.random.normal from one 32-bit draw: sqrt(2)*erfinv(uniform(lo=-1+ulp, 1))
__device__ __forceinline__ float jax_normal(uint32_t bits) {
  float u = __uint_as_float((bits >> 9) | 0x3f800000u) - 1.0f;  // [0,1)
  float r = fmaf(u, 2.0f, -0.99999994f);   // (hi-lo) rounds to 2.0f in f32
  r = fmaxf(-0.99999994f, r);
  return 1.41421356f * jax_erfinv(r);
}

// ---------------- K1: GEMM1 (x @ w1^T + b1) + per-feature partial stats -----
// BM=128 rows/block, BN=48 (full), BK=16. 256 threads: 16x16, each 8 rows x 3 cols.
__global__ __launch_bounds__(256) void gemm1_kernel(const float* __restrict__ x,
                                                    const float* __restrict__ w1,
                                                    const float* __restrict__ b1) {
  __shared__ __align__(16) float As[16][128];
  __shared__ __align__(16) float Ws[16][F1];
  __shared__ float2 red[F1][16];

  const int tid = threadIdx.x;
  const int ty = tid >> 4, tx = tid & 15;
  const int row0 = blockIdx.x * 128;

  float acc[8][3];
#pragma unroll
  for (int i = 0; i < 8; i++)
#pragma unroll
    for (int j = 0; j < 3; j++) acc[i][j] = 0.0f;

  for (int kt = 0; kt < KD; kt += 16) {
    // x tile: 128 rows x 16 k (512 float4), transposed into As[k][row]
#pragma unroll
    for (int l = 0; l < 2; l++) {
      int idx = tid + l * 256;
      int r = idx >> 2, kq = (idx & 3) * 4;
      float4 v = *reinterpret_cast<const float4*>(
          x + (size_t)(row0 + r) * KD + kt + kq);
      As[kq + 0][r] = v.x; As[kq + 1][r] = v.y;
      As[kq + 2][r] = v.z; As[kq + 3][r] = v.w;
    }
    // w tile: 48 x 16 (192 float4) into Ws[k][nf]
    if (tid < 192) {
      int nf = tid >> 2, kq = (tid & 3) * 4;
      float4 v = *reinterpret_cast<const float4*>(
          w1 + (size_t)nf * KD + kt + kq);
      Ws[kq + 0][nf] = v.x; Ws[kq + 1][nf] = v.y;
      Ws[kq + 2][nf] = v.z; Ws[kq + 3][nf] = v.w;
    }
    __syncthreads();
#pragma unroll
    for (int k = 0; k < 16; k++) {
      float4 a03 = *reinterpret_cast<const float4*>(&As[k][ty * 8 + 0]);
      float4 a47 = *reinterpret_cast<const float4*>(&As[k][ty * 8 + 4]);
      float wv0 = Ws[k][tx * 3 + 0];
      float wv1 = Ws[k][tx * 3 + 1];
      float wv2 = Ws[k][tx * 3 + 2];
      acc[0][0] = fmaf(a03.x, wv0, acc[0][0]);
      acc[0][1] = fmaf(a03.x, wv1, acc[0][1]);
      acc[0][2] = fmaf(a03.x, wv2, acc[0][2]);
      acc[1][0] = fmaf(a03.y, wv0, acc[1][0]);
      acc[1][1] = fmaf(a03.y, wv1, acc[1][1]);
      acc[1][2] = fmaf(a03.y, wv2, acc[1][2]);
      acc[2][0] = fmaf(a03.z, wv0, acc[2][0]);
      acc[2][1] = fmaf(a03.z, wv1, acc[2][1]);
      acc[2][2] = fmaf(a03.z, wv2, acc[2][2]);
      acc[3][0] = fmaf(a03.w, wv0, acc[3][0]);
      acc[3][1] = fmaf(a03.w, wv1, acc[3][1]);
      acc[3][2] = fmaf(a03.w, wv2, acc[3][2]);
      acc[4][0] = fmaf(a47.x, wv0, acc[4][0]);
      acc[4][1] = fmaf(a47.x, wv1, acc[4][1]);
      acc[4][2] = fmaf(a47.x, wv2, acc[4][2]);
      acc[5][0] = fmaf(a47.y, wv0, acc[5][0]);
      acc[5][1] = fmaf(a47.y, wv1, acc[5][1]);
      acc[5][2] = fmaf(a47.y, wv2, acc[5][2]);
      acc[6][0] = fmaf(a47.z, wv0, acc[6][0]);
      acc[6][1] = fmaf(a47.z, wv1, acc[6][1]);
      acc[6][2] = fmaf(a47.z, wv2, acc[6][2]);
      acc[7][0] = fmaf(a47.w, wv0, acc[7][0]);
      acc[7][1] = fmaf(a47.w, wv1, acc[7][1]);
      acc[7][2] = fmaf(a47.w, wv2, acc[7][2]);
    }
    __syncthreads();
  }

  // epilogue: add bias, store y1, reduce per-column sum/sumsq
  float bias[3], cs[3] = {0.f, 0.f, 0.f}, css[3] = {0.f, 0.f, 0.f};
#pragma unroll
  for (int j = 0; j < 3; j++) bias[j] = b1[tx * 3 + j];
#pragma unroll
  for (int i = 0; i < 8; i++) {
#pragma unroll
    for (int j = 0; j < 3; j++) {
      float y = acc[i][j] + bias[j];
      int r = ty * 8 + i;
      g_y1[(size_t)(row0 + r) * F1 + tx * 3 + j] = y;
      cs[j] += y;
      css[j] += y * y;
    }
  }
#pragma unroll
  for (int j = 0; j < 3; j++) red[tx * 3 + j][ty] = make_float2(cs[j], css[j]);
  __syncthreads();
  if (tid < F1) {
    float s = 0.f, ss = 0.f;
#pragma unroll
    for (int t = 0; t < 16; t++) { s += red[tid][t].x; ss += red[tid][t].y; }
    g_part1[blockIdx.x][tid][0] = s;
    g_part1[blockIdx.x][tid][1] = ss;
  }
}

// ---------------- finalize: BN params + analytic global mean/std*u ----------
__global__ void finalize_kernel(int layer, const float* __restrict__ gamma,
                                const float* __restrict__ beta, float uval) {
  const int F = (layer == 1) ? F1 : F2;
  const float* base = (layer == 1) ? &g_part1[0][0][0] : &g_part2[0][0][0];
  __shared__ float contrib[F1], betas[F1];
  int f = threadIdx.x;
  if (f < F) {
    float s0 = 0, s1 = 0, s2 = 0, s3 = 0, q0 = 0, q1 = 0, q2 = 0, q3 = 0;
    for (int b = 0; b < NBLK; b += 4) {
      const float* p0 = base + ((size_t)(b + 0) * F + f) * 2;
      const float* p1 = base + ((size_t)(b + 1) * F + f) * 2;
      const float* p2 = base + ((size_t)(b + 2) * F + f) * 2;
      const float* p3 = base + ((size_t)(b + 3) * F + f) * 2;
      s0 += p0[0]; q0 += p0[1];
      s1 += p1[0]; q1 += p1[1];
      s2 += p2[0]; q2 += p2[1];
      s3 += p3[0]; q3 += p3[1];
    }
    double s = (double)s0 + s1 + s2 + s3;
    double ss = (double)q0 + q1 + q2 + q3;
    double mean = s / 65536.0;
    double var = ss / 65536.0 - mean * mean;
    double rr = 1.0 / sqrt(var + 1e-5);
    double g = (double)gamma[f];
    if (layer == 1) {
      g_sc1[f] = (float)(g * rr);
      g_sh1[f] = (float)((double)beta[f] - mean * g * rr);
    } else {
      g_sc2[f] = (float)(g * rr);
      g_sh2[f] = (float)((double)beta[f] - mean * g * rr);
    }
    contrib[f] = (float)(g * g * var / (var + 1e-5));
    betas[f] = beta[f];
  }
  __syncthreads();
  if (f == 0) {
    float bm = 0.f;
    for (int i = 0; i < F; i++) bm += betas[i];
    bm /= (float)F;
    double acc = 0.0;
    for (int i = 0; i < F; i++) {
      double d = (double)betas[i] - bm;
      acc += (double)contrib[i] + d * d;
    }
    double ntot = 65536.0 * (double)F;
    double s2 = 65536.0 * acc / (ntot - 1.0);
    float* msu = (layer == 1) ? g_msu1 : g_msu2;
    msu[0] = bm;                       // global mean of BN output (= mean(beta))
    msu[1] = (float)sqrt(s2) * uval;   // std(ddof=1) * U(1,2)
  }
}

// ---------------- K3: BN1 + noise + relu + GEMM2 + partial stats ------------
__global__ __launch_bounds__(128) void layer2_kernel(const float* __restrict__ w2,
                                                     const float* __restrict__ b2,
                                                     uint32_t kn0, uint32_t kn1) {
  __shared__ __align__(16) float ys[128][49];   // padded: conflict-free row reads
  __shared__ __align__(16) float w2s[F2][F1];
  __shared__ float b2s[F2];
  __shared__ float sc[F1], sh[F1];
  __shared__ __align__(16) float outs[128][F2];

  const int tid = threadIdx.x;
  const int row0 = blockIdx.x * 128;

  const float4* src = reinterpret_cast<const float4*>(g_y1 + (size_t)row0 * F1);
#pragma unroll
  for (int l = 0; l < 12; l++) {
    int idx = tid + l * 128;              // 1536 float4
    float4 v = src[idx];
    int fi = idx * 4, r = fi / F1, c = fi % F1;
    ys[r][c] = v.x; ys[r][c + 1] = v.y; ys[r][c + 2] = v.z; ys[r][c + 3] = v.w;
  }
#pragma unroll
  for (int l = 0; l < 3; l++) {
    int idx = tid + l * 128;
    if (idx < (F2 * F1) / 4) {
      float4 v = reinterpret_cast<const float4*>(w2)[idx];
      float* dst = &w2s[0][0] + idx * 4;
      dst[0] = v.x; dst[1] = v.y; dst[2] = v.z; dst[3] = v.w;
    }
  }
  if (tid < F2) b2s[tid] = b2[tid];
  if (tid < F1) { sc[tid] = g_sc1[tid]; sh[tid] = g_sh1[tid]; }
  const float m1 = g_msu1[0], su1 = g_msu1[1];
  __syncthreads();

  const int grow = row0 + tid;
  const uint32_t ebase = (uint32_t)grow * (uint32_t)F1;
  float acc[F2];
#pragma unroll
  for (int j = 0; j < F2; j++) acc[j] = b2s[j];

  for (int c = 0; c < F1; c++) {
    float z = fmaf(ys[tid][c], sc[c], sh[c]);
    uint32_t bits = jax_bits32(kn0, kn1, ebase + (uint32_t)c);
    float h = fmaxf(z + fmaf(su1, jax_normal(bits), m1), 0.0f);
#pragma unroll
    for (int j = 0; j < F2; j++) acc[j] = fmaf(h, w2s[j][c], acc[j]);
  }
#pragma unroll
  for (int j = 0; j < F2; j++) outs[tid][j] = acc[j];
  __syncthreads();

  if (tid < F2) {
    float s = 0.f, ss = 0.f;
    for (int r = 0; r < 128; r++) {
      float v = outs[r][tid];
      s += v; ss += v * v;
    }
    g_part2[blockIdx.x][tid][0] = s;
    g_part2[blockIdx.x][tid][1] = ss;
  }
  float4* dst = reinterpret_cast<float4*>(g_y2 + (size_t)row0 * F2);
  const float4* osrc = reinterpret_cast<const float4*>(&outs[0][0]);
#pragma unroll
  for (int l = 0; l < 6; l++) dst[tid + l * 128] = osrc[tid + l * 128];
}

// ---------------- K5: BN2 + noise + relu + GEMM3 -> out ---------------------
__global__ __launch_bounds__(128) void layer3_kernel(const float* __restrict__ w3,
                                                     const float* __restrict__ b3,
                                                     float* __restrict__ out,
                                                     uint32_t kn0, uint32_t kn1) {
  __shared__ __align__(16) float ys[128][25];
  __shared__ float w3s[F3][F2];
  __shared__ float b3s[F3];
  __shared__ float sc[F2], sh[F2];
  __shared__ __align__(16) float outs[128][F3];

  const int tid = threadIdx.x;
  const int row0 = blockIdx.x * 128;

  const float4* src = reinterpret_cast<const float4*>(g_y2 + (size_t)row0 * F2);
#pragma unroll
  for (int l = 0; l < 6; l++) {
    int idx = tid + l * 128;              // 768 float4
    float4 v = src[idx];
    int fi = idx * 4, r = fi / F2, c = fi % F2;
    ys[r][c] = v.x; ys[r][c + 1] = v.y; ys[r][c + 2] = v.z; ys[r][c + 3] = v.w;
  }
  // w3 has F3*F2 = 240 elements but only 128 threads: TWO iterations.
  // (Round<=3 bug: single `if (tid < 240)` left w3s[128..239] uninitialized.)
#pragma unroll
  for (int l = 0; l < 2; l++) {
    int idx = tid + l * 128;
    if (idx < F3 * F2) (&w3s[0][0])[idx] = w3[idx];
  }
  if (tid < F3) b3s[tid] = b3[tid];
  if (tid < F2) { sc[tid] = g_sc2[tid]; sh[tid] = g_sh2[tid]; }
  const float m2 = g_msu2[0], su2 = g_msu2[1];
  __syncthreads();

  const int grow = row0 + tid;
  const uint32_t ebase = (uint32_t)grow * (uint32_t)F2;
  float acc[F3];
#pragma unroll
  for (int j = 0; j < F3; j++) acc[j] = b3s[j];

  for (int c = 0; c < F2; c++) {
    float z = fmaf(ys[tid][c], sc[c], sh[c]);
    uint32_t bits = jax_bits32(kn0, kn1, ebase + (uint32_t)c);
    float h = fmaxf(z + fmaf(su2, jax_normal(bits), m2), 0.0f);
#pragma unroll
    for (int j = 0; j < F3; j++) acc[j] = fmaf(h, w3s[j][c], acc[j]);
  }
#pragma unroll
  for (int j = 0; j < F3; j++) outs[tid][j] = acc[j];
  __syncthreads();

  float* dst = out + (size_t)row0 * F3;
  const float* osrc = &outs[0][0];
#pragma unroll
  for (int l = 0; l < F3; l++) dst[tid + l * 128] = osrc[tid + l * 128];
}

// ---------------- host: derive JAX subkeys + uniform scalars ----------------
// JAX >= 0.4.36: jax_threefry_partitionable defaults to True.
//   split(key)[i]   = full output pair of threefry(key, (0, i))
//   bits32(key, e)  = out0 ^ out1 of threefry(key, (0, e))
static void derive_keys(uint32_t seed, uint32_t& kn0, uint32_t& kn1, float& uval) {
  uint32_t k0 = 0u, k1 = seed;
  uint32_t a0, a1, b0, b1;
  tf2x32(k0, k1, 0u, 0u, a0, a1);   // subkey 0 = ku
  tf2x32(k0, k1, 0u, 1u, b0, b1);   // subkey 1 = kn
  kn0 = b0; kn1 = b1;
  uint32_t u0, u1;
  tf2x32(a0, a1, 0u, 0u, u0, u1);   // random_bits(ku, shape=())
  uint32_t bits = u0 ^ u1;
  uint32_t fb = (bits >> 9) | 0x3f800000u;
  float f;
  memcpy(&f, &fb, sizeof(float));
  uval = f;   // uniform(ku, (), minval=1, maxval=2) = [1,2) mantissa draw
}

extern "C" void kernel_launch(void* const* d_in, const int* in_sizes, int n_in,
                              void* d_out, int out_size) {
  const float* x      = (const float*)d_in[0];
  const float* w1     = (const float*)d_in[1];
  const float* b1     = (const float*)d_in[2];
  const float* gamma1 = (const float*)d_in[3];
  const float* beta1  = (const float*)d_in[4];
  const float* w2     = (const float*)d_in[5];
  const float* b2     = (const float*)d_in[6];
  const float* gamma2 = (const float*)d_in[7];
  const float* beta2  = (const float*)d_in[8];
  const float* w3     = (const float*)d_in[9];
  const float* b3     = (const float*)d_in[10];
  float* out = (float*)d_out;

  uint32_t kn10, kn11, kn20, kn21;
  float u1, u2;
  derive_keys(1234u, kn10, kn11, u1);
  derive_keys(5678u, kn20, kn21, u2);

  gemm1_kernel<<<NBLK, 256>>>(x, w1, b1);
  finalize_kernel<<<1, 64>>>(1, gamma1, beta1, u1);
  layer2_kernel<<<NBLK, 128>>>(w2, b2, kn10, kn11);
  finalize_kernel<<<1, 64>>>(2, gamma2, beta2, u2);
  layer3_kernel<<<NBLK, 128>>>(w3, b3, out, kn20, kn21);
}

// round 11
// speedup vs baseline: 1.0309x; 1.0120x over previous
#include <cuda_runtime.h>
#include <cstdint>
#include <cstring>

// Problem constants
#define BATCH 65536
#define KD    784
#define F1    48
#define F2    24
#define F3    10
#define NBLK  512           // BATCH / 128

// ---------------- scratch (device globals; no allocations allowed) ----------
__device__ __align__(16) float g_y1[BATCH * F1];
__device__ __align__(16) float g_y2[BATCH * F2];
__device__ float g_part1[NBLK][F1][2];
__device__ float g_part2[NBLK][F2][2];
__device__ float g_sc1[F1], g_sh1[F1], g_msu1[2];
__device__ float g_sc2[F2], g_sh2[F2], g_msu2[2];

// ---------------- Threefry2x32 (bit-exact JAX) ------------------------------
__host__ __device__ __forceinline__ void tf2x32(uint32_t k0, uint32_t k1,
                                                uint32_t x0, uint32_t x1,
                                                uint32_t& o0, uint32_t& o1) {
  uint32_t ks2 = k0 ^ k1 ^ 0x1BD11BDAu;
  x0 += k0; x1 += k1;
#define TFR(r) { x0 += x1; x1 = (x1 << (r)) | (x1 >> (32 - (r))); x1 ^= x0; }
  TFR(13) TFR(15) TFR(26) TFR(6)
  x0 += k1;  x1 += ks2 + 1u;
  TFR(17) TFR(29) TFR(16) TFR(24)
  x0 += ks2; x1 += k0 + 2u;
  TFR(13) TFR(15) TFR(26) TFR(6)
  x0 += k0;  x1 += k1 + 3u;
  TFR(17) TFR(29) TFR(16) TFR(24)
  x0 += k1;  x1 += ks2 + 4u;
  TFR(13) TFR(15) TFR(26) TFR(6)
  x0 += ks2; x1 += k0 + 5u;
#undef TFR
  o0 = x0; o1 = x1;
}

// JAX partitionable random_bits for 32-bit, element index e (< 2^32):
// counts = (hi64(e)=0, lo64(e)=e); bits = out0 ^ out1.
__device__ __forceinline__ uint32_t jax_bits32(uint32_t k0, uint32_t k1,
                                               uint32_t e) {
  uint32_t o0, o1;
  tf2x32(k0, k1, 0u, e, o0, o1);
  return o0 ^ o1;
}

// XLA/Giles single-precision erfinv (matches jax.lax.erf_inv f32 path)
__device__ __forceinline__ float jax_erfinv(float x) {
  float w = -log1pf(-x * x);
  float p;
  if (w < 5.0f) {
    w -= 2.5f;
    p = 2.81022636e-08f;
    p = fmaf(p, w, 3.43273939e-07f);
    p = fmaf(p, w, -3.5233877e-06f);
    p = fmaf(p, w, -4.39150654e-06f);
    p = fmaf(p, w, 0.00021858087f);
    p = fmaf(p, w, -0.00125372503f);
    p = fmaf(p, w, -0.00417768164f);
    p = fmaf(p, w, 0.246640727f);
    p = fmaf(p, w, 1.50140941f);
  } else {
    w = sqrtf(w) - 3.0f;
    p = -0.000200214257f;
    p = fmaf(p, w, 0.000100950558f);
    p = fmaf(p, w, 0.00134934322f);
    p = fmaf(p, w, -0.00367342844f);
    p = fmaf(p, w, 0.00573950773f);
    p = fmaf(p, w, -0.0076224613f);
    p = fmaf(p, w, 0.00943887047f);
    p = fmaf(p, w, 1.00167406f);
    p = fmaf(p, w, 2.83297682f);
  }
  return p * x;
}

// jax.random.normal from one 32-bit draw: sqrt(2)*erfinv(uniform(lo=-1+ulp, 1))
__device__ __forceinline__ float jax_normal(uint32_t bits) {
  float u = __uint_as_float((bits >> 9) | 0x3f800000u) - 1.0f;  // [0,1)
  float r = fmaf(u, 2.0f, -0.99999994f);   // (hi-lo) rounds to 2.0f in f32
  r = fmaxf(-0.99999994f, r);
  return 1.41421356f * jax_erfinv(r);
}

// ---------------- K1: GEMM1 (x @ w1^T + b1) + per-feature partial stats -----
// BM=128 rows/block, BN=48 (full), BK=16. 256 threads: 16x16, each 8 rows x 3 cols.
__global__ __launch_bounds__(256) void gemm1_kernel(const float* __restrict__ x,
                                                    const float* __restrict__ w1,
                                                    const float* __restrict__ b1) {
  __shared__ __align__(16) float As[16][128];
  __shared__ __align__(16) float Ws[16][F1];
  __shared__ float2 red[F1][16];

  const int tid = threadIdx.x;
  const int ty = tid >> 4, tx = tid & 15;
  const int row0 = blockIdx.x * 128;

  float acc[8][3];
#pragma unroll
  for (int i = 0; i < 8; i++)
#pragma unroll
    for (int j = 0; j < 3; j++) acc[i][j] = 0.0f;

  for (int kt = 0; kt < KD; kt += 16) {
    // x tile: 128 rows x 16 k (512 float4), transposed into As[k][row]
#pragma unroll
    for (int l = 0; l < 2; l++) {
      int idx = tid + l * 256;
      int r = idx >> 2, kq = (idx & 3) * 4;
      float4 v = *reinterpret_cast<const float4*>(
          x + (size_t)(row0 + r) * KD + kt + kq);
      As[kq + 0][r] = v.x; As[kq + 1][r] = v.y;
      As[kq + 2][r] = v.z; As[kq + 3][r] = v.w;
    }
    // w tile: 48 x 16 (192 float4) into Ws[k][nf]
    if (tid < 192) {
      int nf = tid >> 2, kq = (tid & 3) * 4;
      float4 v = *reinterpret_cast<const float4*>(
          w1 + (size_t)nf * KD + kt + kq);
      Ws[kq + 0][nf] = v.x; Ws[kq + 1][nf] = v.y;
      Ws[kq + 2][nf] = v.z; Ws[kq + 3][nf] = v.w;
    }
    __syncthreads();
#pragma unroll
    for (int k = 0; k < 16; k++) {
      float4 a03 = *reinterpret_cast<const float4*>(&As[k][ty * 8 + 0]);
      float4 a47 = *reinterpret_cast<const float4*>(&As[k][ty * 8 + 4]);
      float wv0 = Ws[k][tx * 3 + 0];
      float wv1 = Ws[k][tx * 3 + 1];
      float wv2 = Ws[k][tx * 3 + 2];
      acc[0][0] = fmaf(a03.x, wv0, acc[0][0]);
      acc[0][1] = fmaf(a03.x, wv1, acc[0][1]);
      acc[0][2] = fmaf(a03.x, wv2, acc[0][2]);
      acc[1][0] = fmaf(a03.y, wv0, acc[1][0]);
      acc[1][1] = fmaf(a03.y, wv1, acc[1][1]);
      acc[1][2] = fmaf(a03.y, wv2, acc[1][2]);
      acc[2][0] = fmaf(a03.z, wv0, acc[2][0]);
      acc[2][1] = fmaf(a03.z, wv1, acc[2][1]);
      acc[2][2] = fmaf(a03.z, wv2, acc[2][2]);
      acc[3][0] = fmaf(a03.w, wv0, acc[3][0]);
      acc[3][1] = fmaf(a03.w, wv1, acc[3][1]);
      acc[3][2] = fmaf(a03.w, wv2, acc[3][2]);
      acc[4][0] = fmaf(a47.x, wv0, acc[4][0]);
      acc[4][1] = fmaf(a47.x, wv1, acc[4][1]);
      acc[4][2] = fmaf(a47.x, wv2, acc[4][2]);
      acc[5][0] = fmaf(a47.y, wv0, acc[5][0]);
      acc[5][1] = fmaf(a47.y, wv1, acc[5][1]);
      acc[5][2] = fmaf(a47.y, wv2, acc[5][2]);
      acc[6][0] = fmaf(a47.z, wv0, acc[6][0]);
      acc[6][1] = fmaf(a47.z, wv1, acc[6][1]);
      acc[6][2] = fmaf(a47.z, wv2, acc[6][2]);
      acc[7][0] = fmaf(a47.w, wv0, acc[7][0]);
      acc[7][1] = fmaf(a47.w, wv1, acc[7][1]);
      acc[7][2] = fmaf(a47.w, wv2, acc[7][2]);
    }
    __syncthreads();
  }

  // epilogue: add bias, store y1, reduce per-column sum/sumsq
  float bias[3], cs[3] = {0.f, 0.f, 0.f}, css[3] = {0.f, 0.f, 0.f};
#pragma unroll
  for (int j = 0; j < 3; j++) bias[j] = b1[tx * 3 + j];
#pragma unroll
  for (int i = 0; i < 8; i++) {
#pragma unroll
    for (int j = 0; j < 3; j++) {
      float y = acc[i][j] + bias[j];
      int r = ty * 8 + i;
      g_y1[(size_t)(row0 + r) * F1 + tx * 3 + j] = y;
      cs[j] += y;
      css[j] += y * y;
    }
  }
#pragma unroll
  for (int j = 0; j < 3; j++) red[tx * 3 + j][ty] = make_float2(cs[j], css[j]);
  __syncthreads();
  if (tid < F1) {
    float s = 0.f, ss = 0.f;
#pragma unroll
    for (int t = 0; t < 16; t++) { s += red[tid][t].x; ss += red[tid][t].y; }
    g_part1[blockIdx.x][tid][0] = s;
    g_part1[blockIdx.x][tid][1] = ss;
  }
}

// ---------------- finalize: BN params + analytic global mean/std*u ----------
__global__ void finalize_kernel(int layer, const float* __restrict__ gamma,
                                const float* __restrict__ beta, float uval) {
  const int F = (layer == 1) ? F1 : F2;
  const float* base = (layer == 1) ? &g_part1[0][0][0] : &g_part2[0][0][0];
  __shared__ float contrib[F1], betas[F1];
  int f = threadIdx.x;
  if (f < F) {
    float s0 = 0, s1 = 0, s2 = 0, s3 = 0, q0 = 0, q1 = 0, q2 = 0, q3 = 0;
    for (int b = 0; b < NBLK; b += 4) {
      const float* p0 = base + ((size_t)(b + 0) * F + f) * 2;
      const float* p1 = base + ((size_t)(b + 1) * F + f) * 2;
      const float* p2 = base + ((size_t)(b + 2) * F + f) * 2;
      const float* p3 = base + ((size_t)(b + 3) * F + f) * 2;
      s0 += p0[0]; q0 += p0[1];
      s1 += p1[0]; q1 += p1[1];
      s2 += p2[0]; q2 += p2[1];
      s3 += p3[0]; q3 += p3[1];
    }
    double s = (double)s0 + s1 + s2 + s3;
    double ss = (double)q0 + q1 + q2 + q3;
    double mean = s / 65536.0;
    double var = ss / 65536.0 - mean * mean;
    double rr = 1.0 / sqrt(var + 1e-5);
    double g = (double)gamma[f];
    if (layer == 1) {
      g_sc1[f] = (float)(g * rr);
      g_sh1[f] = (float)((double)beta[f] - mean * g * rr);
    } else {
      g_sc2[f] = (float)(g * rr);
      g_sh2[f] = (float)((double)beta[f] - mean * g * rr);
    }
    contrib[f] = (float)(g * g * var / (var + 1e-5));
    betas[f] = beta[f];
  }
  __syncthreads();
  if (f == 0) {
    float bm = 0.f;
    for (int i = 0; i < F; i++) bm += betas[i];
    bm /= (float)F;
    double acc = 0.0;
    for (int i = 0; i < F; i++) {
      double d = (double)betas[i] - bm;
      acc += (double)contrib[i] + d * d;
    }
    double ntot = 65536.0 * (double)F;
    double s2 = 65536.0 * acc / (ntot - 1.0);
    float* msu = (layer == 1) ? g_msu1 : g_msu2;
    msu[0] = bm;                       // global mean of BN output (= mean(beta))
    msu[1] = (float)sqrt(s2) * uval;   // std(ddof=1) * U(1,2)
  }
}

// ---------------- K3: BN1 + noise + relu + GEMM2 + partial stats ------------
__global__ __launch_bounds__(128) void layer2_kernel(const float* __restrict__ w2,
                                                     const float* __restrict__ b2,
                                                     uint32_t kn0, uint32_t kn1) {
  __shared__ __align__(16) float ys[128][49];   // padded: conflict-free row reads
  __shared__ __align__(16) float w2s[F2][F1];
  __shared__ float b2s[F2];
  __shared__ float sc[F1], sh[F1];
  __shared__ __align__(16) float outs[128][F2];

  const int tid = threadIdx.x;
  const int row0 = blockIdx.x * 128;

  const float4* src = reinterpret_cast<const float4*>(g_y1 + (size_t)row0 * F1);
#pragma unroll
  for (int l = 0; l < 12; l++) {
    int idx = tid + l * 128;              // 1536 float4
    float4 v = src[idx];
    int fi = idx * 4, r = fi / F1, c = fi % F1;
    ys[r][c] = v.x; ys[r][c + 1] = v.y; ys[r][c + 2] = v.z; ys[r][c + 3] = v.w;
  }
#pragma unroll
  for (int l = 0; l < 3; l++) {
    int idx = tid + l * 128;
    if (idx < (F2 * F1) / 4) {
      float4 v = reinterpret_cast<const float4*>(w2)[idx];
      float* dst = &w2s[0][0] + idx * 4;
      dst[0] = v.x; dst[1] = v.y; dst[2] = v.z; dst[3] = v.w;
    }
  }
  if (tid < F2) b2s[tid] = b2[tid];
  if (tid < F1) { sc[tid] = g_sc1[tid]; sh[tid] = g_sh1[tid]; }
  const float m1 = g_msu1[0], su1 = g_msu1[1];
  __syncthreads();

  const int grow = row0 + tid;
  const uint32_t ebase = (uint32_t)grow * (uint32_t)F1;
  float acc[F2];
#pragma unroll
  for (int j = 0; j < F2; j++) acc[j] = b2s[j];

  for (int c = 0; c < F1; c++) {
    float z = fmaf(ys[tid][c], sc[c], sh[c]);
    uint32_t bits = jax_bits32(kn0, kn1, ebase + (uint32_t)c);
    float h = fmaxf(z + fmaf(su1, jax_normal(bits), m1), 0.0f);
#pragma unroll
    for (int j = 0; j < F2; j++) acc[j] = fmaf(h, w2s[j][c], acc[j]);
  }
#pragma unroll
  for (int j = 0; j < F2; j++) outs[tid][j] = acc[j];
  __syncthreads();

  if (tid < F2) {
    float s = 0.f, ss = 0.f;
    for (int r = 0; r < 128; r++) {
      float v = outs[r][tid];
      s += v; ss += v * v;
    }
    g_part2[blockIdx.x][tid][0] = s;
    g_part2[blockIdx.x][tid][1] = ss;
  }
  float4* dst = reinterpret_cast<float4*>(g_y2 + (size_t)row0 * F2);
  const float4* osrc = reinterpret_cast<const float4*>(&outs[0][0]);
#pragma unroll
  for (int l = 0; l < 6; l++) dst[tid + l * 128] = osrc[tid + l * 128];
}

// ---------------- K5: BN2 + noise + relu + GEMM3 -> out ---------------------
__global__ __launch_bounds__(128) void layer3_kernel(const float* __restrict__ w3,
                                                     const float* __restrict__ b3,
                                                     float* __restrict__ out,
                                                     uint32_t kn0, uint32_t kn1) {
  __shared__ __align__(16) float ys[128][25];
  __shared__ float w3s[F3][F2];
  __shared__ float b3s[F3];
  __shared__ float sc[F2], sh[F2];
  __shared__ __align__(16) float outs[128][F3];

  const int tid = threadIdx.x;
  const int row0 = blockIdx.x * 128;

  const float4* src = reinterpret_cast<const float4*>(g_y2 + (size_t)row0 * F2);
#pragma unroll
  for (int l = 0; l < 6; l++) {
    int idx = tid + l * 128;              // 768 float4
    float4 v = src[idx];
    int fi = idx * 4, r = fi / F2, c = fi % F2;
    ys[r][c] = v.x; ys[r][c + 1] = v.y; ys[r][c + 2] = v.z; ys[r][c + 3] = v.w;
  }
  // w3 has F3*F2 = 240 elements but only 128 threads: TWO iterations.
  // (Round<=3 bug: single `if (tid < 240)` left w3s[128..239] uninitialized.)
#pragma unroll
  for (int l = 0; l < 2; l++) {
    int idx = tid + l * 128;
    if (idx < F3 * F2) (&w3s[0][0])[idx] = w3[idx];
  }
  if (tid < F3) b3s[tid] = b3[tid];
  if (tid < F2) { sc[tid] = g_sc2[tid]; sh[tid] = g_sh2[tid]; }
  const float m2 = g_msu2[0], su2 = g_msu2[1];
  __syncthreads();

  const int grow = row0 + tid;
  const uint32_t ebase = (uint32_t)grow * (uint32_t)F2;
  float acc[F3];
#pragma unroll
  for (int j = 0; j < F3; j++) acc[j] = b3s[j];

  for (int c = 0; c < F2; c++) {
    float z = fmaf(ys[tid][c], sc[c], sh[c]);
    uint32_t bits = jax_bits32(kn0, kn1, ebase + (uint32_t)c);
    float h = fmaxf(z + fmaf(su2, jax_normal(bits), m2), 0.0f);
#pragma unroll
    for (int j = 0; j < F3; j++) acc[j] = fmaf(h, w3s[j][c], acc[j]);
  }
#pragma unroll
  for (int j = 0; j < F3; j++) outs[tid][j] = acc[j];
  __syncthreads();

  float* dst = out + (size_t)row0 * F3;
  const float* osrc = &outs[0][0];
#pragma unroll
  for (int l = 0; l < F3; l++) dst[tid + l * 128] = osrc[tid + l * 128];
}

// ---------------- host: derive JAX subkeys + uniform scalars ----------------
// JAX >= 0.4.36: jax_threefry_partitionable defaults to True.
//   split(key)[i]   = full output pair of threefry(key, (0, i))
//   bits32(key, e)  = out0 ^ out1 of threefry(key, (0, e))
static void derive_keys(uint32_t seed, uint32_t& kn0, uint32_t& kn1, float& uval) {
  uint32_t k0 = 0u, k1 = seed;
  uint32_t a0, a1, b0, b1;
  tf2x32(k0, k1, 0u, 0u, a0, a1);   // subkey 0 = ku
  tf2x32(k0, k1, 0u, 1u, b0, b1);   // subkey 1 = kn
  kn0 = b0; kn1 = b1;
  uint32_t u0, u1;
  tf2x32(a0, a1, 0u, 0u, u0, u1);   // random_bits(ku, shape=())
  uint32_t bits = u0 ^ u1;
  uint32_t fb = (bits >> 9) | 0x3f800000u;
  float f;
  memcpy(&f, &fb, sizeof(float));
  uval = f;   // uniform(ku, (), minval=1, maxval=2) = [1,2) mantissa draw
}

extern "C" void kernel_launch(void* const* d_in, const int* in_sizes, int n_in,
                              void* d_out, int out_size) {
  const float* x      = (const float*)d_in[0];
  const float* w1     = (const float*)d_in[1];
  const float* b1     = (const float*)d_in[2];
  const float* gamma1 = (const float*)d_in[3];
  const float* beta1  = (const float*)d_in[4];
  const float* w2     = (const float*)d_in[5];
  const float* b2     = (const float*)d_in[6];
  const float* gamma2 = (const float*)d_in[7];
  const float* beta2  = (const float*)d_in[8];
  const float* w3     = (const float*)d_in[9];
  const float* b3     = (const float*)d_in[10];
  float* out = (float*)d_out;

  uint32_t kn10, kn11, kn20, kn21;
  float u1, u2;
  derive_keys(1234u, kn10, kn11, u1);
  derive_keys(5678u, kn20, kn21, u2);

  gemm1_kernel<<<NBLK, 256>>>(x, w1, b1);
  finalize_kernel<<<1, 64>>>(1, gamma1, beta1, u1);
  layer2_kernel<<<NBLK, 128>>>(w2, b2, kn10, kn11);
  finalize_kernel<<<1, 64>>>(2, gamma2, beta2, u2);
  layer3_kernel<<<NBLK, 128>>>(w3, b3, out, kn20, kn21);
}